// round 1
// baseline (speedup 1.0000x reference)
#include <cuda_runtime.h>
#include <math.h>

#define NB 592          // main-pass blocks (148 SMs * 4)
#define WARPS_PER_BLOCK 8
#define F 128           // feature dim (O_DIM = T_DIM = OUT_F = 128)
#define LOG2E 1.4426950408889634f

// Scratch (allocation-free rule: __device__ globals)
__device__ __align__(16) float g_u[F];     // W_j_w^T @ w_r
__device__ float g_const;                  // w_l . z_i  +  b_j . w_r
__device__ float g_bm[NB];                 // per-block running max
__device__ float g_bl[NB];                 // per-block exp-sum
__device__ __align__(16) float g_bacc[NB][F]; // per-block weighted h_j sum

// ---------------------------------------------------------------------------
// Kernel 0: prep. 1 block, 128 threads.
//   z_i[f] = sum_o W_i_w[f,o]*h_i[o] + b_i[f]
//   const  = sum_f w_l[f]*z_i[f] + sum_f w_r[f]*b_j[f]
//   u[k]   = sum_f w_r[f]*W_j_w[f,k]
// ---------------------------------------------------------------------------
__global__ void prep_kernel(const float* __restrict__ h_i,
                            const float* __restrict__ W_i_w,
                            const float* __restrict__ W_i_b,
                            const float* __restrict__ W_j_w,
                            const float* __restrict__ W_j_b,
                            const float* __restrict__ W_ij) {
    __shared__ float s_hi[F];
    __shared__ float s_wr[F];
    __shared__ float s_part[F];
    int t = threadIdx.x;

    s_hi[t] = h_i[t];
    s_wr[t] = W_ij[F + t];
    __syncthreads();

    // z_i[t]
    float z = W_i_b[t];
    #pragma unroll 8
    for (int o = 0; o < F; o++) z += W_i_w[t * F + o] * s_hi[o];

    float wl = W_ij[t];
    s_part[t] = wl * z + s_wr[t] * W_j_b[t];
    __syncthreads();

    // tree-reduce s_part -> const
    for (int step = F / 2; step > 0; step >>= 1) {
        if (t < step) s_part[t] += s_part[t + step];
        __syncthreads();
    }
    if (t == 0) g_const = s_part[0];

    // u[t] = sum_f wr[f] * W_j_w[f*F + t]  (coalesced across threads)
    float u = 0.f;
    #pragma unroll 8
    for (int f = 0; f < F; f++) u += s_wr[f] * W_j_w[f * F + t];
    g_u[t] = u;
}

// ---------------------------------------------------------------------------
// Kernel 1: streaming pass over h_j with online softmax.
// One warp per row iteration; each lane holds 4 features (float4).
// ---------------------------------------------------------------------------
__global__ __launch_bounds__(WARPS_PER_BLOCK * 32, 4)
void stream_kernel(const float* __restrict__ h_j, int n) {
    const int lane = threadIdx.x & 31;
    const int wid  = threadIdx.x >> 5;
    const int gw   = blockIdx.x * WARPS_PER_BLOCK + wid;
    const int nwarps = gridDim.x * WARPS_PER_BLOCK;

    // register-resident u slice + constant
    const float4 uu = *reinterpret_cast<const float4*>(&g_u[lane * 4]);
    const float  c  = g_const;

    float m = -1e30f, l = 0.f;
    float4 acc = make_float4(0.f, 0.f, 0.f, 0.f);

    for (int r = gw; r < n; r += nwarps) {
        const float4 x = *reinterpret_cast<const float4*>(h_j + (size_t)r * F + lane * 4);
        float p = x.x * uu.x + x.y * uu.y + x.z * uu.z + x.w * uu.w;
        // warp reduce (sum)
        p += __shfl_xor_sync(0xffffffffu, p, 16);
        p += __shfl_xor_sync(0xffffffffu, p, 8);
        p += __shfl_xor_sync(0xffffffffu, p, 4);
        p += __shfl_xor_sync(0xffffffffu, p, 2);
        p += __shfl_xor_sync(0xffffffffu, p, 1);
        float s = p + c;
        float e = (s > 0.f) ? s : 0.1f * s;   // leaky relu

        float mn    = fmaxf(m, e);
        float scale = exp2f((m - mn) * LOG2E);
        float w     = exp2f((e - mn) * LOG2E);
        l = l * scale + w;
        acc.x = acc.x * scale + w * x.x;
        acc.y = acc.y * scale + w * x.y;
        acc.z = acc.z * scale + w * x.z;
        acc.w = acc.w * scale + w * x.w;
        m = mn;
    }

    // combine warps within block
    __shared__ float sm[WARPS_PER_BLOCK];
    __shared__ float sl[WARPS_PER_BLOCK];
    __shared__ float sacc[WARPS_PER_BLOCK][F];
    if (lane == 0) { sm[wid] = m; sl[wid] = l; }
    *reinterpret_cast<float4*>(&sacc[wid][lane * 4]) = acc;
    __syncthreads();

    if (threadIdx.x < F) {
        const int k = threadIdx.x;
        float M = -1e30f;
        #pragma unroll
        for (int w = 0; w < WARPS_PER_BLOCK; w++) M = fmaxf(M, sm[w]);
        float L = 0.f, A = 0.f;
        #pragma unroll
        for (int w = 0; w < WARPS_PER_BLOCK; w++) {
            float sc = exp2f((sm[w] - M) * LOG2E);
            L += sc * sl[w];
            A += sc * sacc[w][k];
        }
        g_bacc[blockIdx.x][k] = A;
        if (k == 0) { g_bm[blockIdx.x] = M; g_bl[blockIdx.x] = L; }
    }
}

// ---------------------------------------------------------------------------
// Kernel 2: cross-block combine + epilogue. 1 block, 128 threads.
//   v = (sum_b exp(m_b-M) acc_b) / (sum_b exp(m_b-M) l_b)
//   h[f] = W_j_w[f,:] . v + b_j[f];  out = h>0 ? h : expm1(h)
// ---------------------------------------------------------------------------
__global__ void finish_kernel(const float* __restrict__ W_j_w,
                              const float* __restrict__ W_j_b,
                              float* __restrict__ out) {
    __shared__ float sv[F];
    const int k = threadIdx.x;

    float M = -1e30f;
    for (int b = 0; b < NB; b++) M = fmaxf(M, g_bm[b]);
    float L = 0.f, A = 0.f;
    for (int b = 0; b < NB; b++) {
        float sc = exp2f((g_bm[b] - M) * LOG2E);
        L += sc * g_bl[b];
        A += sc * g_bacc[b][k];
    }
    sv[k] = A / L;
    __syncthreads();

    float h = W_j_b[k];
    #pragma unroll 8
    for (int j = 0; j < F; j++) h += W_j_w[k * F + j] * sv[j];
    out[k] = (h > 0.f) ? h : expm1f(h);
}

// ---------------------------------------------------------------------------
// kernel_launch
// inputs: 0:h_i 1:h_j 2:W_i_w 3:W_i_b 4:W_j_w 5:W_j_b 6:W_ij
// ---------------------------------------------------------------------------
extern "C" void kernel_launch(void* const* d_in, const int* in_sizes, int n_in,
                              void* d_out, int out_size) {
    const float* h_i   = (const float*)d_in[0];
    const float* h_j   = (const float*)d_in[1];
    const float* W_i_w = (const float*)d_in[2];
    const float* W_i_b = (const float*)d_in[3];
    const float* W_j_w = (const float*)d_in[4];
    const float* W_j_b = (const float*)d_in[5];
    const float* W_ij  = (const float*)d_in[6];
    float* out = (float*)d_out;

    const int n = in_sizes[1] / F;   // number of rows in h_j

    prep_kernel<<<1, 128>>>(h_i, W_i_w, W_i_b, W_j_w, W_j_b, W_ij);
    stream_kernel<<<NB, WARPS_PER_BLOCK * 32>>>(h_j, n);
    finish_kernel<<<1, 128>>>(W_j_w, W_j_b, out);
}

// round 4
// speedup vs baseline: 2.6075x; 2.6075x over previous
#include <cuda_runtime.h>
#include <math.h>

#define NB 592          // main-pass blocks
#define WARPS_PER_BLOCK 8
#define F 128           // O_DIM = T_DIM = OUT_F = 128
#define LOG2E 1.4426950408889634f

// Scratch (allocation-free rule: __device__ globals)
__device__ __align__(16) float g_u[F];        // W_j_w^T @ w_r
__device__ float g_const;                     // w_l . z_i + b_j . w_r
__device__ float g_bm[NB];                    // per-block running max
__device__ float g_bl[NB];                    // per-block exp-sum
__device__ __align__(16) float g_bacc[NB][F]; // per-block weighted h_j sum

__device__ __forceinline__ float warp_red_sum(float v) {
    v += __shfl_xor_sync(0xffffffffu, v, 16);
    v += __shfl_xor_sync(0xffffffffu, v, 8);
    v += __shfl_xor_sync(0xffffffffu, v, 4);
    v += __shfl_xor_sync(0xffffffffu, v, 2);
    v += __shfl_xor_sync(0xffffffffu, v, 1);
    return v;
}
__device__ __forceinline__ float warp_red_max(float v) {
    v = fmaxf(v, __shfl_xor_sync(0xffffffffu, v, 16));
    v = fmaxf(v, __shfl_xor_sync(0xffffffffu, v, 8));
    v = fmaxf(v, __shfl_xor_sync(0xffffffffu, v, 4));
    v = fmaxf(v, __shfl_xor_sync(0xffffffffu, v, 2));
    v = fmaxf(v, __shfl_xor_sync(0xffffffffu, v, 1));
    return v;
}
// fast exp2 via MUFU.EX2
__device__ __forceinline__ float fexp2(float x) {
    float r;
    asm("ex2.approx.ftz.f32 %0, %1;" : "=f"(r) : "f"(x));
    return r;
}

// ---------------------------------------------------------------------------
// Kernel 0: prep. 1 block, 1024 threads.
//   z_i[f] = W_i_w[f,:] . h_i + b_i[f]     (warp per 4 rows, coalesced)
//   u[k]   = sum_f wr[f]*W_j_w[f,k]        (column-parallel, 8-way f split)
//   const  = w_l . z_i + w_r . b_j
// ---------------------------------------------------------------------------
__global__ void prep_kernel(const float* __restrict__ h_i,
                            const float* __restrict__ W_i_w,
                            const float* __restrict__ W_i_b,
                            const float* __restrict__ W_j_w,
                            const float* __restrict__ W_j_b,
                            const float* __restrict__ W_ij) {
    __shared__ __align__(16) float s_hi[F];
    __shared__ __align__(16) float s_wr[F];
    __shared__ __align__(16) float s_z[F];
    __shared__ __align__(16) float s_u[8][F];
    const int t    = threadIdx.x;
    const int lane = t & 31;
    const int w    = t >> 5;

    if (t < F) { s_hi[t] = h_i[t]; s_wr[t] = W_ij[F + t]; }
    __syncthreads();

    // z_i : warp w handles rows 4w..4w+3
    const float4 hh = *reinterpret_cast<const float4*>(&s_hi[lane * 4]);
    #pragma unroll
    for (int r = 0; r < 4; r++) {
        const int f = w * 4 + r;
        const float4 wr4 = *reinterpret_cast<const float4*>(&W_i_w[f * F + lane * 4]);
        float p = wr4.x * hh.x + wr4.y * hh.y + wr4.z * hh.z + wr4.w * hh.w;
        p = warp_red_sum(p);
        if (lane == 0) s_z[f] = p + W_i_b[f];
    }

    // u partials: chunk c = t>>7 handles f in [16c, 16c+16), column col = t&127
    {
        const int c = t >> 7, col = t & 127;
        float u = 0.f;
        #pragma unroll
        for (int ff = 0; ff < 16; ff++) {
            const int f = c * 16 + ff;
            u += s_wr[f] * W_j_w[f * F + col];
        }
        s_u[c][col] = u;
    }
    __syncthreads();

    if (t < F) {
        float u = 0.f;
        #pragma unroll
        for (int c = 0; c < 8; c++) u += s_u[c][t];
        g_u[t] = u;
    }
    // const: warp 0
    if (w == 0) {
        float acc = 0.f;
        #pragma unroll
        for (int f = lane; f < F; f += 32)
            acc += W_ij[f] * s_z[f] + s_wr[f] * W_j_b[f];
        acc = warp_red_sum(acc);
        if (lane == 0) g_const = acc;
    }
}

// ---------------------------------------------------------------------------
// Kernel 1: streaming pass, 4 rows per warp per iteration.
// Lane layout: group g = lane>>3 handles row base+g; sub = lane&7.
// Lane loads 4 float4s (features (q*8+sub)*4 .. +3); group-of-8 reduce = 3 shfl.
// Online softmax state per lane (replicated within group), merged at the end.
// ---------------------------------------------------------------------------
__global__ __launch_bounds__(WARPS_PER_BLOCK * 32)
void stream_kernel(const float* __restrict__ h_j, int n) {
    const int lane = threadIdx.x & 31;
    const int wid  = threadIdx.x >> 5;
    const int sub  = lane & 7;
    const int g    = lane >> 3;

    float4 uu[4];
    #pragma unroll
    for (int q = 0; q < 4; q++)
        uu[q] = *reinterpret_cast<const float4*>(&g_u[(q * 8 + sub) * 4]);
    const float c = g_const;

    float m = -1e30f, l = 0.f;
    float4 acc[4];
    #pragma unroll
    for (int q = 0; q < 4; q++) acc[q] = make_float4(0.f, 0.f, 0.f, 0.f);

    const int nchunks = (n + 3) >> 2;
    const int stride  = gridDim.x * WARPS_PER_BLOCK;

    for (int ch = blockIdx.x * WARPS_PER_BLOCK + wid; ch < nchunks; ch += stride) {
        int row = ch * 4 + g;
        const bool valid = (row < n);
        if (!valid) row = n - 1;
        const float4* rp = reinterpret_cast<const float4*>(h_j + (size_t)row * F);

        float4 x[4];
        #pragma unroll
        for (int q = 0; q < 4; q++) x[q] = __ldcs(&rp[q * 8 + sub]);

        float p = 0.f;
        #pragma unroll
        for (int q = 0; q < 4; q++)
            p += x[q].x * uu[q].x + x[q].y * uu[q].y + x[q].z * uu[q].z + x[q].w * uu[q].w;
        // reduce within 8-lane group (3 shuffles, all 4 rows at once)
        p += __shfl_xor_sync(0xffffffffu, p, 4);
        p += __shfl_xor_sync(0xffffffffu, p, 2);
        p += __shfl_xor_sync(0xffffffffu, p, 1);

        float s = p + c;
        float e = (s > 0.f) ? s : 0.1f * s;
        if (!valid) e = -1e30f;

        const float mn    = fmaxf(m, e);
        const float scale = fexp2((m - mn) * LOG2E);
        const float wgt   = fexp2((e - mn) * LOG2E);
        l = l * scale + wgt;
        #pragma unroll
        for (int q = 0; q < 4; q++) {
            acc[q].x = acc[q].x * scale + wgt * x[q].x;
            acc[q].y = acc[q].y * scale + wgt * x[q].y;
            acc[q].z = acc[q].z * scale + wgt * x[q].z;
            acc[q].w = acc[q].w * scale + wgt * x[q].w;
        }
        m = mn;
    }

    // ---- merge the 4 groups within the warp (xor 8, 16) ----
    float M = m;
    M = fmaxf(M, __shfl_xor_sync(0xffffffffu, M, 8));
    M = fmaxf(M, __shfl_xor_sync(0xffffffffu, M, 16));
    const float sc = fexp2((m - M) * LOG2E);
    float L = l * sc;
    L += __shfl_xor_sync(0xffffffffu, L, 8);
    L += __shfl_xor_sync(0xffffffffu, L, 16);
    #pragma unroll
    for (int q = 0; q < 4; q++) {
        float a;
        a = acc[q].x * sc; a += __shfl_xor_sync(0xffffffffu, a, 8); a += __shfl_xor_sync(0xffffffffu, a, 16); acc[q].x = a;
        a = acc[q].y * sc; a += __shfl_xor_sync(0xffffffffu, a, 8); a += __shfl_xor_sync(0xffffffffu, a, 16); acc[q].y = a;
        a = acc[q].z * sc; a += __shfl_xor_sync(0xffffffffu, a, 8); a += __shfl_xor_sync(0xffffffffu, a, 16); acc[q].z = a;
        a = acc[q].w * sc; a += __shfl_xor_sync(0xffffffffu, a, 8); a += __shfl_xor_sync(0xffffffffu, a, 16); acc[q].w = a;
    }

    // ---- merge warps within block ----
    __shared__ __align__(16) float sm[WARPS_PER_BLOCK];
    __shared__ __align__(16) float sl[WARPS_PER_BLOCK];
    __shared__ __align__(16) float sacc[WARPS_PER_BLOCK][F];
    if (g == 0) {
        #pragma unroll
        for (int q = 0; q < 4; q++)
            *reinterpret_cast<float4*>(&sacc[wid][(q * 8 + sub) * 4]) = acc[q];
        if (sub == 0) { sm[wid] = M; sl[wid] = L; }
    }
    __syncthreads();

    if (threadIdx.x < F) {
        const int k = threadIdx.x;
        float BM = -1e30f;
        #pragma unroll
        for (int w = 0; w < WARPS_PER_BLOCK; w++) BM = fmaxf(BM, sm[w]);
        float BL = 0.f, BA = 0.f;
        #pragma unroll
        for (int w = 0; w < WARPS_PER_BLOCK; w++) {
            const float ws = fexp2((sm[w] - BM) * LOG2E);
            BL += ws * sl[w];
            BA += ws * sacc[w][k];
        }
        g_bacc[blockIdx.x][k] = BA;
        if (k == 0) { g_bm[blockIdx.x] = BM; g_bl[blockIdx.x] = BL; }
    }
}

// ---------------------------------------------------------------------------
// Kernel 2: cross-block combine + epilogue. 1 block, 1024 threads.
// ---------------------------------------------------------------------------
__global__ void finish_kernel(const float* __restrict__ W_j_w,
                              const float* __restrict__ W_j_b,
                              float* __restrict__ out) {
    __shared__ __align__(16) float s_red[32];
    __shared__ float sMv;
    __shared__ __align__(16) float sL[8];
    __shared__ __align__(16) float sA[8][F];
    __shared__ __align__(16) float sv[F];
    const int t    = threadIdx.x;
    const int lane = t & 31;
    const int w    = t >> 5;

    // global max over NB blocks
    float lm = -1e30f;
    for (int b = t; b < NB; b += 1024) lm = fmaxf(lm, g_bm[b]);
    lm = warp_red_max(lm);
    if (lane == 0) s_red[w] = lm;
    __syncthreads();
    if (t < 32) {
        float v = s_red[t];
        v = warp_red_max(v);
        if (t == 0) sMv = v;
    }
    __syncthreads();
    const float M = sMv;

    // 8-way split of the block loop: chunk c handles blocks c, c+8, ...
    {
        const int c = t >> 7, k = t & 127;
        float L = 0.f, A = 0.f;
        for (int b = c; b < NB; b += 8) {
            const float sc = fexp2((g_bm[b] - M) * LOG2E);
            L += sc * g_bl[b];
            A += sc * g_bacc[b][k];
        }
        sA[c][k] = A;
        if (k == 0) sL[c] = L;
    }
    __syncthreads();

    if (t < F) {
        float A = 0.f, L = 0.f;
        #pragma unroll
        for (int c = 0; c < 8; c++) { A += sA[c][t]; L += sL[c]; }
        sv[t] = A / L;
    }
    __syncthreads();

    // matvec + activation: warp w handles rows 4w..4w+3
    const float4 vv = *reinterpret_cast<const float4*>(&sv[lane * 4]);
    #pragma unroll
    for (int r = 0; r < 4; r++) {
        const int k = w * 4 + r;
        const float4 wr4 = *reinterpret_cast<const float4*>(&W_j_w[k * F + lane * 4]);
        float p = wr4.x * vv.x + wr4.y * vv.y + wr4.z * vv.z + wr4.w * vv.w;
        p = warp_red_sum(p);
        if (lane == 0) {
            const float h = p + W_j_b[k];
            out[k] = (h > 0.f) ? h : expm1f(h);
        }
    }
}

// ---------------------------------------------------------------------------
// kernel_launch — inputs: 0:h_i 1:h_j 2:W_i_w 3:W_i_b 4:W_j_w 5:W_j_b 6:W_ij
// ---------------------------------------------------------------------------
extern "C" void kernel_launch(void* const* d_in, const int* in_sizes, int n_in,
                              void* d_out, int out_size) {
    const float* h_i   = (const float*)d_in[0];
    const float* h_j   = (const float*)d_in[1];
    const float* W_i_w = (const float*)d_in[2];
    const float* W_i_b = (const float*)d_in[3];
    const float* W_j_w = (const float*)d_in[4];
    const float* W_j_b = (const float*)d_in[5];
    const float* W_ij  = (const float*)d_in[6];
    float* out = (float*)d_out;

    const int n = in_sizes[1] / F;

    prep_kernel<<<1, 1024>>>(h_i, W_i_w, W_i_b, W_j_w, W_j_b, W_ij);
    stream_kernel<<<NB, WARPS_PER_BLOCK * 32>>>(h_j, n);
    finish_kernel<<<1, 1024>>>(W_j_w, W_j_b, out);
}